// round 7
// baseline (speedup 1.0000x reference)
#include <cuda_runtime.h>
#include <cuda_bf16.h>
#include <math.h>

// ---------------- scratch (device globals; no allocation) ----------------
__device__ float g_gi[25165824];    // 65536 x 384
__device__ float g_short[8388608];  // 65536 x 128
__device__ float g_WB1[24576];      // Whh1 bf16 [384][128] (as float storage)
__device__ float g_WiB[3072];       // Wih1 bf16 [384][16]
__device__ float g_WB4[24576];      // gaWhh bf16 [384][128]
__device__ float g_intra[262144];
__device__ float g_lg[262144];
__device__ float g_la[262144];
__device__ float g_Wh[262144];
__device__ float g_s12[4096];
__device__ float g_sec[2048];
__device__ float g_Wh2[2048];
__device__ float g_s12b[32];
__device__ float g_secout[2048];

// ---------------- helpers ----------------
__device__ __forceinline__ float sigmoidf_(float x) {
    return __fdividef(1.f, 1.f + __expf(-x));
}
__device__ __forceinline__ float tanhapx_(float x) {
    float y; asm("tanh.approx.f32 %0, %1;" : "=f"(y) : "f"(x)); return y;
}
__device__ __forceinline__ float sigapx_(float x) {
    return fmaf(tanhapx_(0.5f * x), 0.5f, 0.5f);
}
__device__ __forceinline__ void mma_bf16(float d[4], unsigned a0, unsigned a1,
                                         unsigned a2, unsigned a3,
                                         unsigned b0, unsigned b1) {
    asm volatile(
        "mma.sync.aligned.m16n8k16.row.col.f32.bf16.bf16.f32 "
        "{%0,%1,%2,%3},{%4,%5,%6,%7},{%8,%9},{%0,%1,%2,%3};\n"
        : "+f"(d[0]), "+f"(d[1]), "+f"(d[2]), "+f"(d[3])
        : "r"(a0), "r"(a1), "r"(a2), "r"(a3), "r"(b0), "r"(b1));
}
__device__ __forceinline__ void ldsm4(unsigned& r0, unsigned& r1, unsigned& r2,
                                      unsigned& r3, unsigned addr) {
    asm volatile("ldmatrix.sync.aligned.m8n8.x4.shared.b16 {%0,%1,%2,%3}, [%4];\n"
        : "=r"(r0), "=r"(r1), "=r"(r2), "=r"(r3) : "r"(addr));
}
__device__ __forceinline__ float blockReduceSum128(float v, float* red) {
    #pragma unroll
    for (int o = 16; o; o >>= 1) v += __shfl_xor_sync(0xffffffffu, v, o);
    int w = threadIdx.x >> 5;
    if ((threadIdx.x & 31) == 0) red[w] = v;
    __syncthreads();
    float s = red[0] + red[1] + red[2] + red[3];
    __syncthreads();
    return s;
}

// ---------------- fp32 -> bf16 convert ----------------
__global__ void conv_bf16(const float* __restrict__ W, __nv_bfloat16* __restrict__ O, int n) {
    int i = blockIdx.x * 256 + threadIdx.x;
    if (i < n) O[i] = __float2bfloat16(W[i]);
}

// ---------------- bf16 tensor-core GRU, fused attention pooling ----------------
// MT m16-tiles of sequences per CTA (SEQ=16*MT), 512 thr = 16 warps;
// warp w owns cols w*8 of each gate block. Whh bf16 B-frags in registers.
// Full T-history of h kept as bf16 in smem; A-fragments loaded via ldmatrix.
template<int T, bool XMMA, int MT>
__global__ void __launch_bounds__(512, 1) gru_mma(
    const float* __restrict__ xin,          // XMMA: x rows of 80; else gi [(seq*T+t)][384]
    const __nv_bfloat16* __restrict__ WiB,  // XMMA: Wih bf16 [384][16]
    const __nv_bfloat16* __restrict__ WB,   // Whh bf16 [384][128]
    const float* __restrict__ bih,          // XMMA only
    const float* __restrict__ bhh,
    const float* __restrict__ aw, const float* __restrict__ ab,
    float* __restrict__ outp)               // [seq][128] pooled
{
    constexpr int SEQ = 16 * MT;
    extern __shared__ char smc[];
    __nv_bfloat16* hsm = (__nv_bfloat16*)smc;           // [T][SEQ][136]
    __nv_bfloat16* x_b = hsm + T * SEQ * 136;           // XMMA: [SEQ][88]
    float* sc_s = (float*)(x_b + (XMMA ? SEQ * 88 : 0)); // [SEQ][T]

    int tid = threadIdx.x;
    int w = tid >> 5, lane = tid & 31;
    int g = lane >> 2, tig = lane & 3;
    size_t seq0 = (size_t)blockIdx.x * SEQ;
    int c0 = w * 8 + 2 * tig;

    // ldmatrix lane byte-offsets (row = lane&15, k-half = lane>>4)
    unsigned lrow = lane & 15, lko = (lane >> 4) * 8;
    unsigned lofs_h = (lrow * 136 + lko) * 2;
    unsigned lofs_x = (lrow * 88 + lko) * 2;
    unsigned hsm_sh = (unsigned)__cvta_generic_to_shared(hsm);
    unsigned xb_sh  = (unsigned)__cvta_generic_to_shared(x_b);

    if (XMMA) {
        for (int i = tid; i < SEQ * 80; i += 512)
            x_b[(i / 80) * 88 + (i % 80)] = __float2bfloat16(__ldg(xin + seq0 * 80 + i));
    }
    // Whh bf16 B-fragments: wb[kt][gate][reg], col = gate*128 + w*8 + g
    unsigned wb[8][3][2];
    #pragma unroll
    for (int kt = 0; kt < 8; kt++) {
        #pragma unroll
        for (int nt = 0; nt < 3; nt++) {
            const __nv_bfloat16* p = WB + (size_t)(nt * 128 + w * 8 + g) * 128 + kt * 16;
            wb[kt][nt][0] = *(const unsigned*)(p + 2 * tig);
            wb[kt][nt][1] = *(const unsigned*)(p + 8 + 2 * tig);
        }
    }
    unsigned wbi[3][2];
    if (XMMA) {
        #pragma unroll
        for (int nt = 0; nt < 3; nt++) {
            const __nv_bfloat16* p = WiB + (size_t)(nt * 128 + w * 8 + g) * 16;
            wbi[nt][0] = *(const unsigned*)(p + 2 * tig);
            wbi[nt][1] = *(const unsigned*)(p + 8 + 2 * tig);
        }
    }
    float2 bhr2 = *(const float2*)(bhh + c0);
    float2 bhz2 = *(const float2*)(bhh + 128 + c0);
    float2 bhn2 = *(const float2*)(bhh + 256 + c0);
    float2 bir2 = {0, 0}, biz2 = {0, 0}, bin2 = {0, 0};
    if (XMMA) {
        bir2 = *(const float2*)(bih + c0);
        biz2 = *(const float2*)(bih + 128 + c0);
        bin2 = *(const float2*)(bih + 256 + c0);
    }
    __syncthreads();

    for (int t = 0; t < T; t++) {
        float aR[MT][4], aZ[MT][4], aN[MT][4], aI[MT][4];
        #pragma unroll
        for (int mt = 0; mt < MT; mt++)
            #pragma unroll
            for (int q = 0; q < 4; q++) {
                aR[mt][q] = 0.f; aZ[mt][q] = 0.f; aN[mt][q] = 0.f; aI[mt][q] = 0.f;
            }
        float2 pgr[MT][2], pgz[MT][2], pgn[MT][2];

        if (!XMMA) {
            // prefetch gi early so latency overlaps the MMA phase
            #pragma unroll
            for (int mt = 0; mt < MT; mt++)
                #pragma unroll
                for (int hh = 0; hh < 2; hh++) {
                    int row = mt * 16 + (hh ? g + 8 : g);
                    const float* gp = xin + ((seq0 + row) * (size_t)T + t) * 384;
                    pgr[mt][hh] = *(const float2*)(gp + c0);
                    pgz[mt][hh] = *(const float2*)(gp + 128 + c0);
                    pgn[mt][hh] = *(const float2*)(gp + 256 + c0);
                }
        } else {
            // gi = x @ Wih^T (single k16 MMA per gate per tile)
            #pragma unroll
            for (int mt = 0; mt < MT; mt++) {
                unsigned a0, a1, a2, a3;
                ldsm4(a0, a1, a2, a3, xb_sh + mt * 16 * 88 * 2 + lofs_x + t * 32);
                mma_bf16(aR[mt], a0, a1, a2, a3, wbi[0][0], wbi[0][1]);
                mma_bf16(aZ[mt], a0, a1, a2, a3, wbi[1][0], wbi[1][1]);
                mma_bf16(aI[mt], a0, a1, a2, a3, wbi[2][0], wbi[2][1]);
            }
        }
        if (t > 0) {
            unsigned hbase = hsm_sh + (unsigned)((t - 1) * SEQ * 136 * 2);
            #pragma unroll
            for (int kt = 0; kt < 8; kt++) {
                #pragma unroll
                for (int mt = 0; mt < MT; mt++) {
                    unsigned a0, a1, a2, a3;
                    ldsm4(a0, a1, a2, a3, hbase + mt * 16 * 136 * 2 + lofs_h + kt * 32);
                    mma_bf16(aR[mt], a0, a1, a2, a3, wb[kt][0][0], wb[kt][0][1]);
                    mma_bf16(aZ[mt], a0, a1, a2, a3, wb[kt][1][0], wb[kt][1][1]);
                    mma_bf16(aN[mt], a0, a1, a2, a3, wb[kt][2][0], wb[kt][2][1]);
                }
            }
        }
        // in-register gate update on fragments
        {
            __nv_bfloat16* hcur = hsm + (size_t)t * SEQ * 136;
            const __nv_bfloat16* hprv = hsm + (size_t)(t > 0 ? t - 1 : 0) * SEQ * 136;
            #pragma unroll
            for (int mt = 0; mt < MT; mt++)
                #pragma unroll
                for (int hh = 0; hh < 2; hh++) {
                    int row = mt * 16 + (hh ? g + 8 : g);
                    int e = hh * 2;
                    float gr0 = aR[mt][e] + bhr2.x, gr1 = aR[mt][e + 1] + bhr2.y;
                    float gz0 = aZ[mt][e] + bhz2.x, gz1 = aZ[mt][e + 1] + bhz2.y;
                    float gn0 = aN[mt][e] + bhn2.x, gn1 = aN[mt][e + 1] + bhn2.y;
                    float in0, in1;
                    if (XMMA) {
                        gr0 += bir2.x; gr1 += bir2.y;
                        gz0 += biz2.x; gz1 += biz2.y;
                        in0 = aI[mt][e] + bin2.x; in1 = aI[mt][e + 1] + bin2.y;
                    } else {
                        gr0 += pgr[mt][hh].x; gr1 += pgr[mt][hh].y;
                        gz0 += pgz[mt][hh].x; gz1 += pgz[mt][hh].y;
                        in0 = pgn[mt][hh].x; in1 = pgn[mt][hh].y;
                    }
                    float r0 = sigapx_(gr0), r1 = sigapx_(gr1);
                    float z0 = sigapx_(gz0), z1 = sigapx_(gz1);
                    float n0 = tanhapx_(fmaf(r0, gn0, in0));
                    float n1 = tanhapx_(fmaf(r1, gn1, in1));
                    float h0, h1;
                    if (t == 0) {
                        h0 = (1.f - z0) * n0;
                        h1 = (1.f - z1) * n1;
                    } else {
                        float2 hp2 = __bfloat1622float2(
                            *(const __nv_bfloat162*)(hprv + row * 136 + c0));
                        h0 = fmaf(z0, hp2.x - n0, n0);
                        h1 = fmaf(z1, hp2.y - n1, n1);
                    }
                    *(__nv_bfloat162*)(hcur + row * 136 + c0) =
                        __float22bfloat162_rn(make_float2(h0, h1));
                }
        }
        __syncthreads();
    }

    // fused attention pooling over T (h history in bf16 smem)
    float ab0 = __ldg(ab);
    {
        float awv[4];
        #pragma unroll
        for (int q = 0; q < 4; q++) awv[q] = __ldg(aw + lane + 32 * q);
        for (int s = w; s < SEQ; s += 16) {
            for (int t = 0; t < T; t++) {
                float v = 0.f;
                #pragma unroll
                for (int q = 0; q < 4; q++)
                    v = fmaf(__bfloat162float(hsm[t * SEQ * 136 + s * 136 + lane + 32 * q]),
                             awv[q], v);
                #pragma unroll
                for (int o = 16; o; o >>= 1) v += __shfl_xor_sync(0xffffffffu, v, o);
                if (lane == 0) sc_s[s * T + t] = v + ab0;
            }
        }
    }
    __syncthreads();
    {
        int j = tid & 127, sb = tid >> 7;
        for (int s = sb; s < SEQ; s += 4) {
            float m = -1e30f;
            for (int t = 0; t < T; t++) m = fmaxf(m, sc_s[s * T + t]);
            float Z = 0.f, acc = 0.f;
            for (int t = 0; t < T; t++) {
                float wt = __expf(sc_s[s * T + t] - m);
                Z += wt;
                acc = fmaf(wt, __bfloat162float(hsm[t * SEQ * 136 + s * 136 + j]), acc);
            }
            outp[(seq0 + s) * 128 + j] = acc / Z;
        }
    }
}

// ---------------- bf16 GEMM: C[M,384] = A[M,128] @ W[384,128]^T + bias ----------------
__global__ void __launch_bounds__(256) gemm_bf16(
    const float* __restrict__ A, const float* __restrict__ W,
    const float* __restrict__ bias, float* __restrict__ C)
{
    extern __shared__ char gsc[];
    __nv_bfloat16* As = (__nv_bfloat16*)gsc;  // 64 x 136
    __nv_bfloat16* Ws = As + 64 * 136;        // 64 x 136
    int tid = threadIdx.x;
    size_t m0 = (size_t)blockIdx.x * 64;
    int n0 = blockIdx.y * 64;
    for (int i = tid; i < 2048; i += 256) {
        int r = i >> 5, c4 = (i & 31) * 4;
        float4 av = *(const float4*)(A + (m0 + r) * 128 + c4);
        float4 wv = *(const float4*)(W + (size_t)(n0 + r) * 128 + c4);
        *(__nv_bfloat162*)(As + r * 136 + c4)     = __float22bfloat162_rn(make_float2(av.x, av.y));
        *(__nv_bfloat162*)(As + r * 136 + c4 + 2) = __float22bfloat162_rn(make_float2(av.z, av.w));
        *(__nv_bfloat162*)(Ws + r * 136 + c4)     = __float22bfloat162_rn(make_float2(wv.x, wv.y));
        *(__nv_bfloat162*)(Ws + r * 136 + c4 + 2) = __float22bfloat162_rn(make_float2(wv.z, wv.w));
    }
    __syncthreads();
    int w = tid >> 5, lane = tid & 31;
    int wm = w & 3, wn = w >> 2;
    int g = lane >> 2, tig = lane & 3;
    int mrow = wm * 16, nbase = wn * 32;
    unsigned lofs = ((lane & 15) * 136 + (lane >> 4) * 8) * 2;
    unsigned as_sh = (unsigned)__cvta_generic_to_shared(As);
    float d[4][4] = {};
    #pragma unroll
    for (int k0 = 0; k0 < 128; k0 += 16) {
        unsigned a0, a1, a2, a3;
        ldsm4(a0, a1, a2, a3, as_sh + mrow * 136 * 2 + lofs + k0 * 2);
        int kc = k0 + 2 * tig;
        #pragma unroll
        for (int f = 0; f < 4; f++) {
            unsigned b0 = *(const unsigned*)(Ws + (nbase + f * 8 + g) * 136 + kc);
            unsigned b1 = *(const unsigned*)(Ws + (nbase + f * 8 + g) * 136 + kc + 8);
            mma_bf16(d[f], a0, a1, a2, a3, b0, b1);
        }
    }
    #pragma unroll
    for (int f = 0; f < 4; f++) {
        int col = n0 + nbase + f * 8 + 2 * tig;
        float2 b2 = *(const float2*)(bias + col);
        *(float2*)(C + (m0 + mrow + g) * 384 + col) =
            make_float2(d[f][0] + b2.x, d[f][1] + b2.y);
        *(float2*)(C + (m0 + mrow + g + 8) * 384 + col) =
            make_float2(d[f][2] + b2.x, d[f][3] + b2.y);
    }
}

// ---------------- single-step GRU with h0=0 (stage 3) ----------------
__global__ void gru_single(const float* __restrict__ gi, const float* __restrict__ bhh,
                           float* __restrict__ lg)
{
    int idx = blockIdx.x * 256 + threadIdx.x;
    int s = idx >> 7, j = idx & 127;
    const float* gp = gi + (size_t)s * 384;
    float r = sigmoidf_(__ldg(gp + j) + __ldg(bhh + j));
    float z = sigmoidf_(__ldg(gp + 128 + j) + __ldg(bhh + 128 + j));
    float n = tanhf(__ldg(gp + 256 + j) + r * __ldg(bhh + 256 + j));
    lg[idx] = (1.f - z) * n;
}

// ---------------- GAT prep ----------------
__global__ void __launch_bounds__(128) gat_prep(
    const float* __restrict__ Hin, int rstride,
    const float* __restrict__ W, const float* __restrict__ a,
    float* __restrict__ Wh, float* __restrict__ s12, int M)
{
    __shared__ float red[4];
    int m = blockIdx.x, n = threadIdx.x;
    const float* hr = Hin + (size_t)m * rstride;
    float acc = 0.f;
    #pragma unroll 8
    for (int k = 0; k < 128; k++) acc = fmaf(__ldg(hr + k), W[k * 128 + n], acc);
    Wh[(size_t)m * 128 + n] = acc;
    float s1 = blockReduceSum128(acc * __ldg(a + n), red);
    float s2 = blockReduceSum128(acc * __ldg(a + 128 + n), red);
    if (n == 0) { s12[m] = s1; s12[M + m] = s2; }
}

// ---------------- GAT intra attention ----------------
__global__ void __launch_bounds__(128) gat_intra_attn(
    const float* __restrict__ Wh, const float* __restrict__ s12,
    const int* __restrict__ sect, float* __restrict__ out)
{
    __shared__ float red[4];
    __shared__ int lst[2048];
    __shared__ float wgt[2048];
    __shared__ int cnt;
    int i = blockIdx.x, d = threadIdx.x;
    if (d == 0) cnt = 0;
    __syncthreads();
    int si = __ldg(sect + i);
    for (int j = d; j < 2048; j += 128)
        if (__ldg(sect + j) == si) { int p = atomicAdd(&cnt, 1); lst[p] = j; }
    __syncthreads();
    int n = cnt;
    float s1i = s12[i];
    float lm = -1e30f;
    for (int p = d; p < n; p += 128) {
        float e = s1i + s12[2048 + lst[p]];
        e = e >= 0.f ? e : 0.2f * e;
        lm = fmaxf(lm, e);
    }
    #pragma unroll
    for (int o = 16; o; o >>= 1) lm = fmaxf(lm, __shfl_xor_sync(0xffffffffu, lm, o));
    if ((d & 31) == 0) red[d >> 5] = lm;
    __syncthreads();
    float m = fmaxf(fmaxf(red[0], red[1]), fmaxf(red[2], red[3]));
    __syncthreads();
    float lz = 0.f;
    for (int p = d; p < n; p += 128) {
        float e = s1i + s12[2048 + lst[p]];
        e = e >= 0.f ? e : 0.2f * e;
        float w = __expf(e - m);
        wgt[p] = w;
        lz += w;
    }
    float Z = blockReduceSum128(lz, red);
    float inv = __fdividef(1.f, Z);
    float acc = 0.f;
    #pragma unroll 4
    for (int p = 0; p < n; p++) acc = fmaf(wgt[p], Wh[(size_t)lst[p] * 128 + d], acc);
    acc *= inv;
    out[(size_t)i * 128 + d] = acc > 0.f ? acc : expm1f(acc);
}

// ---------------- sector mean ----------------
__global__ void __launch_bounds__(128) sector_mean(
    const float* __restrict__ lg, const int* __restrict__ sect, float* __restrict__ sec)
{
    int ns = blockIdx.x, d = threadIdx.x;
    float s = 0.f;
    int c = 0;
    for (int i = 0; i < 2048; i++) {
        if (__ldg(sect + i) == ns) { s += lg[(size_t)i * 128 + d]; c++; }
    }
    sec[ns * 128 + d] = s / fmaxf((float)c, 1.f);
}

// ---------------- GAT inter attention ----------------
__global__ void __launch_bounds__(128) gat_inter_attn(
    const float* __restrict__ Wh, const float* __restrict__ s12,
    const int* __restrict__ adj, float* __restrict__ out)
{
    __shared__ float e[16];
    int i = blockIdx.x, d = threadIdx.x;
    if (d < 16) {
        float v = s12[i] + s12[16 + d];
        v = v >= 0.f ? v : 0.2f * v;
        e[d] = (__ldg(adj + i * 16 + d) > 0) ? v : -9.0e15f;
    }
    __syncthreads();
    float m = -1e30f;
    #pragma unroll
    for (int j = 0; j < 16; j++) m = fmaxf(m, e[j]);
    float Z = 0.f, acc = 0.f;
    #pragma unroll
    for (int j = 0; j < 16; j++) {
        float w = __expf(e[j] - m);
        Z += w;
        acc = fmaf(w, Wh[j * 128 + d], acc);
    }
    acc = __fdividef(acc, Z);
    out[i * 128 + d] = acc > 0.f ? acc : expm1f(acc);
}

// ---------------- fusion + heads ----------------
__global__ void __launch_bounds__(128) fusion_heads(
    const float* __restrict__ lg, const float* __restrict__ la,
    const float* __restrict__ secout, const int* __restrict__ sect,
    const float* __restrict__ fw, const float* __restrict__ fb,
    const float* __restrict__ rw, const float* __restrict__ rb,
    const float* __restrict__ mw, const float* __restrict__ mb,
    float* __restrict__ out)
{
    __shared__ float red[4];
    int i = blockIdx.x, n = threadIdx.x;
    int si = __ldg(sect + i);
    const float* lgr = lg + (size_t)i * 128;
    const float* lar = la + (size_t)i * 128;
    const float* ser = secout + (size_t)si * 128;
    float acc = __ldg(fb + n);
    #pragma unroll 4
    for (int k = 0; k < 128; k++) acc = fmaf(__ldg(lgr + k), fw[k * 128 + n], acc);
    #pragma unroll 4
    for (int k = 0; k < 128; k++) acc = fmaf(__ldg(lar + k), fw[(128 + k) * 128 + n], acc);
    #pragma unroll 4
    for (int k = 0; k < 128; k++) acc = fmaf(__ldg(ser + k), fw[(256 + k) * 128 + n], acc);
    float r  = blockReduceSum128(acc * __ldg(rw + n), red);
    float mv = blockReduceSum128(acc * __ldg(mw + n), red);
    if (n == 0) {
        out[i]        = r + __ldg(rb);
        out[2048 + i] = sigmoidf_(mv + __ldg(mb));
    }
}

// ---------------- launch ----------------
extern "C" void kernel_launch(void* const* d_in, const int* in_sizes, int n_in,
                              void* d_out, int out_size)
{
    const float* sf    = (const float*)d_in[0];
    const int*   sect  = (const int*)d_in[1];
    const int*   adj   = (const int*)d_in[2];
    const float* g1Wih = (const float*)d_in[3];
    const float* g1Whh = (const float*)d_in[4];
    const float* g1bih = (const float*)d_in[5];
    const float* g1bhh = (const float*)d_in[6];
    const float* a1w   = (const float*)d_in[7];
    const float* a1b   = (const float*)d_in[8];
    const float* giW   = (const float*)d_in[9];
    const float* gia   = (const float*)d_in[10];
    const float* ggWih = (const float*)d_in[11];
    const float* ggWhh = (const float*)d_in[12];
    const float* ggbih = (const float*)d_in[13];
    const float* ggbhh = (const float*)d_in[14];
    const float* agw   = (const float*)d_in[15];
    const float* agb   = (const float*)d_in[16];
    const float* gaWih = (const float*)d_in[17];
    const float* gaWhh = (const float*)d_in[18];
    const float* gabih = (const float*)d_in[19];
    const float* gabhh = (const float*)d_in[20];
    const float* aaw   = (const float*)d_in[21];
    const float* aab   = (const float*)d_in[22];
    const float* geW   = (const float*)d_in[23];
    const float* gea   = (const float*)d_in[24];
    const float* fw    = (const float*)d_in[25];
    const float* fb    = (const float*)d_in[26];
    const float* rw    = (const float*)d_in[27];
    const float* rb    = (const float*)d_in[28];
    const float* mw    = (const float*)d_in[29];
    const float* mb    = (const float*)d_in[30];
    float* out = (float*)d_out;

    float *gi, *shortb, *WB1f, *WiBf, *WB4f, *intra, *lgv, *lav, *Wh, *s12, *sec, *Wh2, *s12b, *secout;
    cudaGetSymbolAddress((void**)&gi, g_gi);
    cudaGetSymbolAddress((void**)&shortb, g_short);
    cudaGetSymbolAddress((void**)&WB1f, g_WB1);
    cudaGetSymbolAddress((void**)&WiBf, g_WiB);
    cudaGetSymbolAddress((void**)&WB4f, g_WB4);
    cudaGetSymbolAddress((void**)&intra, g_intra);
    cudaGetSymbolAddress((void**)&lgv, g_lg);
    cudaGetSymbolAddress((void**)&lav, g_la);
    cudaGetSymbolAddress((void**)&Wh, g_Wh);
    cudaGetSymbolAddress((void**)&s12, g_s12);
    cudaGetSymbolAddress((void**)&sec, g_sec);
    cudaGetSymbolAddress((void**)&Wh2, g_Wh2);
    cudaGetSymbolAddress((void**)&s12b, g_s12b);
    cudaGetSymbolAddress((void**)&secout, g_secout);
    __nv_bfloat16* WB1 = (__nv_bfloat16*)WB1f;
    __nv_bfloat16* WiB = (__nv_bfloat16*)WiBf;
    __nv_bfloat16* WB4 = (__nv_bfloat16*)WB4f;

    const int smem1 = 5 * 32 * 136 * 2 + 32 * 88 * 2 + 32 * 5 * 4;   // 49792
    const int smem4 = 32 * 16 * 136 * 2 + 16 * 32 * 4;               // 141312
    const int smemG = 2 * 64 * 136 * 2;                              // 34816
    cudaFuncSetAttribute(gru_mma<5, true, 2>,
                         cudaFuncAttributeMaxDynamicSharedMemorySize, smem1);
    cudaFuncSetAttribute(gru_mma<32, false, 1>,
                         cudaFuncAttributeMaxDynamicSharedMemorySize, smem4);

    // weight conversions to bf16
    conv_bf16<<<(49152 + 255) / 256, 256>>>(g1Whh, WB1, 49152);
    conv_bf16<<<(6144 + 255) / 256, 256>>>(g1Wih, WiB, 6144);
    conv_bf16<<<(49152 + 255) / 256, 256>>>(gaWhh, WB4, 49152);

    // Stage 1: fused GRU1 + attention over 65536 sequences (T=5, F=16), 32 seqs/CTA
    gru_mma<5, true, 2><<<2048, 512, smem1>>>(
        sf, WiB, WB1, g1bih, g1bhh, a1w, a1b, shortb);

    // Stage 2: intra-sector GAT on last week's embedding
    gat_prep<<<2048, 128>>>(shortb + 31 * 128, 32 * 128, giW, gia, Wh, s12, 2048);
    gat_intra_attn<<<2048, 128>>>(Wh, s12, sect, intra);

    // Stage 3: lg = single-step GRU (h0=0, T=1 attn = identity)
    gemm_bf16<<<dim3(2048 / 64, 6), 256, smemG>>>(intra, ggWih, ggbih, gi);
    gru_single<<<1024, 256>>>(gi, ggbhh, lgv);

    // Stage 4: la = GRU over 32 weekly embeddings (T=32), pooling fused
    gemm_bf16<<<dim3(65536 / 64, 6), 256, smemG>>>(shortb, gaWih, gabih, gi);
    gru_mma<32, false, 1><<<128, 512, smem4>>>(
        gi, nullptr, WB4, nullptr, gabhh, aaw, aab, lav);

    // Stage 5: sector aggregation + inter-sector GAT
    sector_mean<<<16, 128>>>(lgv, sect, sec);
    gat_prep<<<16, 128>>>(sec, 128, geW, gea, Wh2, s12b, 16);
    gat_inter_attn<<<16, 128>>>(Wh2, s12b, adj, secout);

    // Stage 6: fusion + heads
    fusion_heads<<<2048, 128>>>(lgv, lav, secout, sect, fw, fb, rw, rb, mw, mb, out);
}

// round 8
// speedup vs baseline: 1.4642x; 1.4642x over previous
#include <cuda_runtime.h>
#include <cuda_bf16.h>
#include <math.h>

// ---------------- scratch (device globals; no allocation) ----------------
__device__ float g_gi[25165824];    // 65536 x 384
__device__ float g_short[8388608];  // 65536 x 128
__device__ float g_WB1[24576];      // Whh1 bf16 [384][128] (as float storage)
__device__ float g_WiB[3072];       // Wih1 bf16 [384][16]
__device__ float g_WB4[24576];      // gaWhh bf16 [384][128]
__device__ float g_intra[262144];
__device__ float g_lg[262144];
__device__ float g_la[262144];
__device__ float g_Wh[262144];
__device__ float g_s12[4096];
__device__ float g_sec[2048];
__device__ float g_Wh2[2048];
__device__ float g_s12b[32];
__device__ float g_secout[2048];

// ---------------- helpers ----------------
__device__ __forceinline__ float sigmoidf_(float x) {
    return __fdividef(1.f, 1.f + __expf(-x));
}
__device__ __forceinline__ float tanhapx_(float x) {
    float y; asm("tanh.approx.f32 %0, %1;" : "=f"(y) : "f"(x)); return y;
}
__device__ __forceinline__ float sigapx_(float x) {
    return fmaf(tanhapx_(0.5f * x), 0.5f, 0.5f);
}
__device__ __forceinline__ void mma_bf16(float d[4], unsigned a0, unsigned a1,
                                         unsigned a2, unsigned a3,
                                         unsigned b0, unsigned b1) {
    asm volatile(
        "mma.sync.aligned.m16n8k16.row.col.f32.bf16.bf16.f32 "
        "{%0,%1,%2,%3},{%4,%5,%6,%7},{%8,%9},{%0,%1,%2,%3};\n"
        : "+f"(d[0]), "+f"(d[1]), "+f"(d[2]), "+f"(d[3])
        : "r"(a0), "r"(a1), "r"(a2), "r"(a3), "r"(b0), "r"(b1));
}
__device__ __forceinline__ float blockReduceSum128(float v, float* red) {
    #pragma unroll
    for (int o = 16; o; o >>= 1) v += __shfl_xor_sync(0xffffffffu, v, o);
    int w = threadIdx.x >> 5;
    if ((threadIdx.x & 31) == 0) red[w] = v;
    __syncthreads();
    float s = red[0] + red[1] + red[2] + red[3];
    __syncthreads();
    return s;
}

// ---------------- fp32 -> bf16 convert ----------------
__global__ void conv_bf16(const float* __restrict__ W, __nv_bfloat16* __restrict__ O, int n) {
    int i = blockIdx.x * 256 + threadIdx.x;
    if (i < n) O[i] = __float2bfloat16(W[i]);
}

// ---------------- bf16 tensor-core GRU, fused attention pooling, persistent ----------------
// 16 seqs per batch; grid-stride loop over nBatch batches. 512 thr = 16 warps;
// warp w owns cols w*8 of each gate block. Whh bf16 B-frags in registers (48),
// loaded ONCE per CTA. Full T-history of h kept as bf16 in smem.
template<int T, bool XMMA>
__global__ void __launch_bounds__(512, 1) gru_mma(
    const float* __restrict__ xin,          // XMMA: x rows of 80; else gi [(seq*T+t)][384]
    const __nv_bfloat16* __restrict__ WiB,  // XMMA: Wih bf16 [384][16]
    const __nv_bfloat16* __restrict__ WB,   // Whh bf16 [384][128]
    const float* __restrict__ bih,          // XMMA only
    const float* __restrict__ bhh,
    const float* __restrict__ aw, const float* __restrict__ ab,
    float* __restrict__ outp,               // [seq][128] pooled
    int nBatch)
{
    extern __shared__ char smc[];
    __nv_bfloat16* hsm = (__nv_bfloat16*)smc;           // [T][16][136]
    __nv_bfloat16* x_b = hsm + T * 16 * 136;            // XMMA: [16][88]
    float* sc_s = (float*)(x_b + (XMMA ? 16 * 88 : 0)); // [16][T]

    int tid = threadIdx.x;
    int w = tid >> 5, lane = tid & 31;
    int g = lane >> 2, tig = lane & 3;
    int c0 = w * 8 + 2 * tig;

    // ---- one-time prologue: weight fragments into registers ----
    unsigned wb[8][3][2];
    #pragma unroll
    for (int kt = 0; kt < 8; kt++) {
        #pragma unroll
        for (int nt = 0; nt < 3; nt++) {
            const __nv_bfloat16* p = WB + (size_t)(nt * 128 + w * 8 + g) * 128 + kt * 16;
            wb[kt][nt][0] = *(const unsigned*)(p + 2 * tig);
            wb[kt][nt][1] = *(const unsigned*)(p + 8 + 2 * tig);
        }
    }
    unsigned wbi[3][2];
    if (XMMA) {
        #pragma unroll
        for (int nt = 0; nt < 3; nt++) {
            const __nv_bfloat16* p = WiB + (size_t)(nt * 128 + w * 8 + g) * 16;
            wbi[nt][0] = *(const unsigned*)(p + 2 * tig);
            wbi[nt][1] = *(const unsigned*)(p + 8 + 2 * tig);
        }
    }
    float2 bhr2 = *(const float2*)(bhh + c0);
    float2 bhz2 = *(const float2*)(bhh + 128 + c0);
    float2 bhn2 = *(const float2*)(bhh + 256 + c0);
    float2 bir2 = {0, 0}, biz2 = {0, 0}, bin2 = {0, 0};
    if (XMMA) {
        bir2 = *(const float2*)(bih + c0);
        biz2 = *(const float2*)(bih + 128 + c0);
        bin2 = *(const float2*)(bih + 256 + c0);
    }
    float ab0 = __ldg(ab);
    float awv[4];
    #pragma unroll
    for (int q = 0; q < 4; q++) awv[q] = __ldg(aw + lane + 32 * q);

    // ---- persistent batch loop ----
    for (int b = blockIdx.x; b < nBatch; b += gridDim.x) {
        size_t seq0 = (size_t)b * 16;

        if (XMMA) {
            for (int i = tid; i < 16 * 80; i += 512)
                x_b[(i / 80) * 88 + (i % 80)] = __float2bfloat16(__ldg(xin + seq0 * 80 + i));
        }
        // barrier: x_b ready AND previous batch's pooling reads of hsm complete
        __syncthreads();

        for (int t = 0; t < T; t++) {
            float ra[4] = {0, 0, 0, 0}, rb[4] = {0, 0, 0, 0};
            float za[4] = {0, 0, 0, 0}, zb[4] = {0, 0, 0, 0};
            float na[4] = {0, 0, 0, 0}, nb[4] = {0, 0, 0, 0};
            float gn_[4] = {0, 0, 0, 0};
            float2 pgr[2], pgz[2], pgn[2];

            if (!XMMA) {
                // prefetch gi early so latency overlaps the MMA phase
                #pragma unroll
                for (int hh = 0; hh < 2; hh++) {
                    int row = hh ? g + 8 : g;
                    const float* gp = xin + ((seq0 + row) * (size_t)T + t) * 384;
                    pgr[hh] = *(const float2*)(gp + c0);
                    pgz[hh] = *(const float2*)(gp + 128 + c0);
                    pgn[hh] = *(const float2*)(gp + 256 + c0);
                }
            } else {
                // gi = x @ Wih^T (single k16 MMA per gate)
                int kc = t * 16 + 2 * tig;
                unsigned a0 = *(const unsigned*)(x_b + g * 88 + kc);
                unsigned a1 = *(const unsigned*)(x_b + (g + 8) * 88 + kc);
                unsigned a2 = *(const unsigned*)(x_b + g * 88 + kc + 8);
                unsigned a3 = *(const unsigned*)(x_b + (g + 8) * 88 + kc + 8);
                mma_bf16(ra, a0, a1, a2, a3, wbi[0][0], wbi[0][1]);
                mma_bf16(za, a0, a1, a2, a3, wbi[1][0], wbi[1][1]);
                mma_bf16(gn_, a0, a1, a2, a3, wbi[2][0], wbi[2][1]);
            }
            if (t > 0) {
                const __nv_bfloat16* hb = hsm + (size_t)(t - 1) * 16 * 136;
                #pragma unroll
                for (int kt = 0; kt < 8; kt++) {
                    int kc = kt * 16 + 2 * tig;
                    unsigned a0 = *(const unsigned*)(hb + g * 136 + kc);
                    unsigned a1 = *(const unsigned*)(hb + (g + 8) * 136 + kc);
                    unsigned a2 = *(const unsigned*)(hb + g * 136 + kc + 8);
                    unsigned a3 = *(const unsigned*)(hb + (g + 8) * 136 + kc + 8);
                    if (kt & 1) {
                        mma_bf16(rb, a0, a1, a2, a3, wb[kt][0][0], wb[kt][0][1]);
                        mma_bf16(zb, a0, a1, a2, a3, wb[kt][1][0], wb[kt][1][1]);
                        mma_bf16(nb, a0, a1, a2, a3, wb[kt][2][0], wb[kt][2][1]);
                    } else {
                        mma_bf16(ra, a0, a1, a2, a3, wb[kt][0][0], wb[kt][0][1]);
                        mma_bf16(za, a0, a1, a2, a3, wb[kt][1][0], wb[kt][1][1]);
                        mma_bf16(na, a0, a1, a2, a3, wb[kt][2][0], wb[kt][2][1]);
                    }
                }
            }
            // in-register gate update on fragments
            {
                __nv_bfloat16* hcur = hsm + (size_t)t * 16 * 136;
                const __nv_bfloat16* hprv = hsm + (size_t)(t > 0 ? t - 1 : 0) * 16 * 136;
                #pragma unroll
                for (int hh = 0; hh < 2; hh++) {
                    int row = hh ? g + 8 : g;
                    int e = hh * 2;
                    float gr0 = ra[e] + rb[e] + bhr2.x, gr1 = ra[e + 1] + rb[e + 1] + bhr2.y;
                    float gz0 = za[e] + zb[e] + bhz2.x, gz1 = za[e + 1] + zb[e + 1] + bhz2.y;
                    float gn0 = na[e] + nb[e] + bhn2.x, gn1 = na[e + 1] + nb[e + 1] + bhn2.y;
                    float in0, in1;
                    if (XMMA) {
                        gr0 += bir2.x; gr1 += bir2.y;
                        gz0 += biz2.x; gz1 += biz2.y;
                        in0 = gn_[e] + bin2.x; in1 = gn_[e + 1] + bin2.y;
                    } else {
                        gr0 += pgr[hh].x; gr1 += pgr[hh].y;
                        gz0 += pgz[hh].x; gz1 += pgz[hh].y;
                        in0 = pgn[hh].x; in1 = pgn[hh].y;
                    }
                    float r0 = sigapx_(gr0), r1 = sigapx_(gr1);
                    float z0 = sigapx_(gz0), z1 = sigapx_(gz1);
                    float n0 = tanhapx_(fmaf(r0, gn0, in0));
                    float n1 = tanhapx_(fmaf(r1, gn1, in1));
                    float h0, h1;
                    if (t == 0) {
                        h0 = (1.f - z0) * n0;
                        h1 = (1.f - z1) * n1;
                    } else {
                        float2 hp2 = __bfloat1622float2(
                            *(const __nv_bfloat162*)(hprv + row * 136 + c0));
                        h0 = fmaf(z0, hp2.x - n0, n0);
                        h1 = fmaf(z1, hp2.y - n1, n1);
                    }
                    *(__nv_bfloat162*)(hcur + row * 136 + c0) =
                        __float22bfloat162_rn(make_float2(h0, h1));
                }
            }
            __syncthreads();
        }

        // fused attention pooling over T (h history in bf16 smem)
        {
            int s = w;  // 16 warps = 16 seqs
            for (int t = 0; t < T; t++) {
                float v = 0.f;
                #pragma unroll
                for (int q = 0; q < 4; q++)
                    v = fmaf(__bfloat162float(hsm[t * 16 * 136 + s * 136 + lane + 32 * q]),
                             awv[q], v);
                #pragma unroll
                for (int o = 16; o; o >>= 1) v += __shfl_xor_sync(0xffffffffu, v, o);
                if (lane == 0) sc_s[s * T + t] = v + ab0;
            }
        }
        __syncthreads();
        {
            int j = tid & 127, sb = tid >> 7;
            #pragma unroll
            for (int i = 0; i < 4; i++) {
                int s = sb + i * 4;
                float m = -1e30f;
                for (int t = 0; t < T; t++) m = fmaxf(m, sc_s[s * T + t]);
                float Z = 0.f, acc = 0.f;
                for (int t = 0; t < T; t++) {
                    float wt = __expf(sc_s[s * T + t] - m);
                    Z += wt;
                    acc = fmaf(wt, __bfloat162float(hsm[t * 16 * 136 + s * 136 + j]), acc);
                }
                outp[(seq0 + s) * 128 + j] = acc / Z;
            }
        }
        // next loop iteration's leading __syncthreads() protects hsm reuse
    }
}

// ---------------- bf16 GEMM: C[M,384] = A[M,128] @ W[384,128]^T + bias ----------------
__global__ void __launch_bounds__(256) gemm_bf16(
    const float* __restrict__ A, const float* __restrict__ W,
    const float* __restrict__ bias, float* __restrict__ C)
{
    extern __shared__ char gsc[];
    __nv_bfloat16* As = (__nv_bfloat16*)gsc;  // 64 x 136
    __nv_bfloat16* Ws = As + 64 * 136;        // 64 x 136
    int tid = threadIdx.x;
    size_t m0 = (size_t)blockIdx.x * 64;
    int n0 = blockIdx.y * 64;
    for (int i = tid; i < 2048; i += 256) {
        int r = i >> 5, c4 = (i & 31) * 4;
        float4 av = *(const float4*)(A + (m0 + r) * 128 + c4);
        float4 wv = *(const float4*)(W + (size_t)(n0 + r) * 128 + c4);
        *(__nv_bfloat162*)(As + r * 136 + c4)     = __float22bfloat162_rn(make_float2(av.x, av.y));
        *(__nv_bfloat162*)(As + r * 136 + c4 + 2) = __float22bfloat162_rn(make_float2(av.z, av.w));
        *(__nv_bfloat162*)(Ws + r * 136 + c4)     = __float22bfloat162_rn(make_float2(wv.x, wv.y));
        *(__nv_bfloat162*)(Ws + r * 136 + c4 + 2) = __float22bfloat162_rn(make_float2(wv.z, wv.w));
    }
    __syncthreads();
    int w = tid >> 5, lane = tid & 31;
    int wm = w & 3, wn = w >> 2;
    int g = lane >> 2, tig = lane & 3;
    int mrow = wm * 16, nbase = wn * 32;
    float d[4][4] = {};
    #pragma unroll
    for (int k0 = 0; k0 < 128; k0 += 16) {
        int kc = k0 + 2 * tig;
        unsigned a0 = *(const unsigned*)(As + (mrow + g) * 136 + kc);
        unsigned a1 = *(const unsigned*)(As + (mrow + g + 8) * 136 + kc);
        unsigned a2 = *(const unsigned*)(As + (mrow + g) * 136 + kc + 8);
        unsigned a3 = *(const unsigned*)(As + (mrow + g + 8) * 136 + kc + 8);
        #pragma unroll
        for (int f = 0; f < 4; f++) {
            unsigned b0 = *(const unsigned*)(Ws + (nbase + f * 8 + g) * 136 + kc);
            unsigned b1 = *(const unsigned*)(Ws + (nbase + f * 8 + g) * 136 + kc + 8);
            mma_bf16(d[f], a0, a1, a2, a3, b0, b1);
        }
    }
    #pragma unroll
    for (int f = 0; f < 4; f++) {
        int col = n0 + nbase + f * 8 + 2 * tig;
        float2 b2 = *(const float2*)(bias + col);
        *(float2*)(C + (m0 + mrow + g) * 384 + col) =
            make_float2(d[f][0] + b2.x, d[f][1] + b2.y);
        *(float2*)(C + (m0 + mrow + g + 8) * 384 + col) =
            make_float2(d[f][2] + b2.x, d[f][3] + b2.y);
    }
}

// ---------------- single-step GRU with h0=0 (stage 3) ----------------
__global__ void gru_single(const float* __restrict__ gi, const float* __restrict__ bhh,
                           float* __restrict__ lg)
{
    int idx = blockIdx.x * 256 + threadIdx.x;
    int s = idx >> 7, j = idx & 127;
    const float* gp = gi + (size_t)s * 384;
    float r = sigmoidf_(__ldg(gp + j) + __ldg(bhh + j));
    float z = sigmoidf_(__ldg(gp + 128 + j) + __ldg(bhh + 128 + j));
    float n = tanhf(__ldg(gp + 256 + j) + r * __ldg(bhh + 256 + j));
    lg[idx] = (1.f - z) * n;
}

// ---------------- GAT prep ----------------
__global__ void __launch_bounds__(128) gat_prep(
    const float* __restrict__ Hin, int rstride,
    const float* __restrict__ W, const float* __restrict__ a,
    float* __restrict__ Wh, float* __restrict__ s12, int M)
{
    __shared__ float red[4];
    int m = blockIdx.x, n = threadIdx.x;
    const float* hr = Hin + (size_t)m * rstride;
    float acc = 0.f;
    #pragma unroll 8
    for (int k = 0; k < 128; k++) acc = fmaf(__ldg(hr + k), W[k * 128 + n], acc);
    Wh[(size_t)m * 128 + n] = acc;
    float s1 = blockReduceSum128(acc * __ldg(a + n), red);
    float s2 = blockReduceSum128(acc * __ldg(a + 128 + n), red);
    if (n == 0) { s12[m] = s1; s12[M + m] = s2; }
}

// ---------------- GAT intra attention ----------------
__global__ void __launch_bounds__(128) gat_intra_attn(
    const float* __restrict__ Wh, const float* __restrict__ s12,
    const int* __restrict__ sect, float* __restrict__ out)
{
    __shared__ float red[4];
    __shared__ int lst[2048];
    __shared__ float wgt[2048];
    __shared__ int cnt;
    int i = blockIdx.x, d = threadIdx.x;
    if (d == 0) cnt = 0;
    __syncthreads();
    int si = __ldg(sect + i);
    for (int j = d; j < 2048; j += 128)
        if (__ldg(sect + j) == si) { int p = atomicAdd(&cnt, 1); lst[p] = j; }
    __syncthreads();
    int n = cnt;
    float s1i = s12[i];
    float lm = -1e30f;
    for (int p = d; p < n; p += 128) {
        float e = s1i + s12[2048 + lst[p]];
        e = e >= 0.f ? e : 0.2f * e;
        lm = fmaxf(lm, e);
    }
    #pragma unroll
    for (int o = 16; o; o >>= 1) lm = fmaxf(lm, __shfl_xor_sync(0xffffffffu, lm, o));
    if ((d & 31) == 0) red[d >> 5] = lm;
    __syncthreads();
    float m = fmaxf(fmaxf(red[0], red[1]), fmaxf(red[2], red[3]));
    __syncthreads();
    float lz = 0.f;
    for (int p = d; p < n; p += 128) {
        float e = s1i + s12[2048 + lst[p]];
        e = e >= 0.f ? e : 0.2f * e;
        float w = __expf(e - m);
        wgt[p] = w;
        lz += w;
    }
    float Z = blockReduceSum128(lz, red);
    float inv = __fdividef(1.f, Z);
    float acc = 0.f;
    #pragma unroll 4
    for (int p = 0; p < n; p++) acc = fmaf(wgt[p], Wh[(size_t)lst[p] * 128 + d], acc);
    acc *= inv;
    out[(size_t)i * 128 + d] = acc > 0.f ? acc : expm1f(acc);
}

// ---------------- sector mean ----------------
__global__ void __launch_bounds__(128) sector_mean(
    const float* __restrict__ lg, const int* __restrict__ sect, float* __restrict__ sec)
{
    int ns = blockIdx.x, d = threadIdx.x;
    float s = 0.f;
    int c = 0;
    for (int i = 0; i < 2048; i++) {
        if (__ldg(sect + i) == ns) { s += lg[(size_t)i * 128 + d]; c++; }
    }
    sec[ns * 128 + d] = s / fmaxf((float)c, 1.f);
}

// ---------------- GAT inter attention ----------------
__global__ void __launch_bounds__(128) gat_inter_attn(
    const float* __restrict__ Wh, const float* __restrict__ s12,
    const int* __restrict__ adj, float* __restrict__ out)
{
    __shared__ float e[16];
    int i = blockIdx.x, d = threadIdx.x;
    if (d < 16) {
        float v = s12[i] + s12[16 + d];
        v = v >= 0.f ? v : 0.2f * v;
        e[d] = (__ldg(adj + i * 16 + d) > 0) ? v : -9.0e15f;
    }
    __syncthreads();
    float m = -1e30f;
    #pragma unroll
    for (int j = 0; j < 16; j++) m = fmaxf(m, e[j]);
    float Z = 0.f, acc = 0.f;
    #pragma unroll
    for (int j = 0; j < 16; j++) {
        float w = __expf(e[j] - m);
        Z += w;
        acc = fmaf(w, Wh[j * 128 + d], acc);
    }
    acc = __fdividef(acc, Z);
    out[i * 128 + d] = acc > 0.f ? acc : expm1f(acc);
}

// ---------------- fusion + heads ----------------
__global__ void __launch_bounds__(128) fusion_heads(
    const float* __restrict__ lg, const float* __restrict__ la,
    const float* __restrict__ secout, const int* __restrict__ sect,
    const float* __restrict__ fw, const float* __restrict__ fb,
    const float* __restrict__ rw, const float* __restrict__ rb,
    const float* __restrict__ mw, const float* __restrict__ mb,
    float* __restrict__ out)
{
    __shared__ float red[4];
    int i = blockIdx.x, n = threadIdx.x;
    int si = __ldg(sect + i);
    const float* lgr = lg + (size_t)i * 128;
    const float* lar = la + (size_t)i * 128;
    const float* ser = secout + (size_t)si * 128;
    float acc = __ldg(fb + n);
    #pragma unroll 4
    for (int k = 0; k < 128; k++) acc = fmaf(__ldg(lgr + k), fw[k * 128 + n], acc);
    #pragma unroll 4
    for (int k = 0; k < 128; k++) acc = fmaf(__ldg(lar + k), fw[(128 + k) * 128 + n], acc);
    #pragma unroll 4
    for (int k = 0; k < 128; k++) acc = fmaf(__ldg(ser + k), fw[(256 + k) * 128 + n], acc);
    float r  = blockReduceSum128(acc * __ldg(rw + n), red);
    float mv = blockReduceSum128(acc * __ldg(mw + n), red);
    if (n == 0) {
        out[i]        = r + __ldg(rb);
        out[2048 + i] = sigmoidf_(mv + __ldg(mb));
    }
}

// ---------------- launch ----------------
extern "C" void kernel_launch(void* const* d_in, const int* in_sizes, int n_in,
                              void* d_out, int out_size)
{
    const float* sf    = (const float*)d_in[0];
    const int*   sect  = (const int*)d_in[1];
    const int*   adj   = (const int*)d_in[2];
    const float* g1Wih = (const float*)d_in[3];
    const float* g1Whh = (const float*)d_in[4];
    const float* g1bih = (const float*)d_in[5];
    const float* g1bhh = (const float*)d_in[6];
    const float* a1w   = (const float*)d_in[7];
    const float* a1b   = (const float*)d_in[8];
    const float* giW   = (const float*)d_in[9];
    const float* gia   = (const float*)d_in[10];
    const float* ggWih = (const float*)d_in[11];
    const float* ggWhh = (const float*)d_in[12];
    const float* ggbih = (const float*)d_in[13];
    const float* ggbhh = (const float*)d_in[14];
    const float* agw   = (const float*)d_in[15];
    const float* agb   = (const float*)d_in[16];
    const float* gaWih = (const float*)d_in[17];
    const float* gaWhh = (const float*)d_in[18];
    const float* gabih = (const float*)d_in[19];
    const float* gabhh = (const float*)d_in[20];
    const float* aaw   = (const float*)d_in[21];
    const float* aab   = (const float*)d_in[22];
    const float* geW   = (const float*)d_in[23];
    const float* gea   = (const float*)d_in[24];
    const float* fw    = (const float*)d_in[25];
    const float* fb    = (const float*)d_in[26];
    const float* rw    = (const float*)d_in[27];
    const float* rb    = (const float*)d_in[28];
    const float* mw    = (const float*)d_in[29];
    const float* mb    = (const float*)d_in[30];
    float* out = (float*)d_out;

    float *gi, *shortb, *WB1f, *WiBf, *WB4f, *intra, *lgv, *lav, *Wh, *s12, *sec, *Wh2, *s12b, *secout;
    cudaGetSymbolAddress((void**)&gi, g_gi);
    cudaGetSymbolAddress((void**)&shortb, g_short);
    cudaGetSymbolAddress((void**)&WB1f, g_WB1);
    cudaGetSymbolAddress((void**)&WiBf, g_WiB);
    cudaGetSymbolAddress((void**)&WB4f, g_WB4);
    cudaGetSymbolAddress((void**)&intra, g_intra);
    cudaGetSymbolAddress((void**)&lgv, g_lg);
    cudaGetSymbolAddress((void**)&lav, g_la);
    cudaGetSymbolAddress((void**)&Wh, g_Wh);
    cudaGetSymbolAddress((void**)&s12, g_s12);
    cudaGetSymbolAddress((void**)&sec, g_sec);
    cudaGetSymbolAddress((void**)&Wh2, g_Wh2);
    cudaGetSymbolAddress((void**)&s12b, g_s12b);
    cudaGetSymbolAddress((void**)&secout, g_secout);
    __nv_bfloat16* WB1 = (__nv_bfloat16*)WB1f;
    __nv_bfloat16* WiB = (__nv_bfloat16*)WiBf;
    __nv_bfloat16* WB4 = (__nv_bfloat16*)WB4f;

    const int smem1 = 5 * 16 * 136 * 2 + 16 * 88 * 2 + 16 * 5 * 4;   // 24896
    const int smem4 = 32 * 16 * 136 * 2 + 16 * 32 * 4;               // 141312
    const int smemG = 2 * 64 * 136 * 2;                              // 34816
    cudaFuncSetAttribute(gru_mma<5, true>,
                         cudaFuncAttributeMaxDynamicSharedMemorySize, smem1);
    cudaFuncSetAttribute(gru_mma<32, false>,
                         cudaFuncAttributeMaxDynamicSharedMemorySize, smem4);

    // weight conversions to bf16
    conv_bf16<<<(49152 + 255) / 256, 256>>>(g1Whh, WB1, 49152);
    conv_bf16<<<(6144 + 255) / 256, 256>>>(g1Wih, WiB, 6144);
    conv_bf16<<<(49152 + 255) / 256, 256>>>(gaWhh, WB4, 49152);

    // Stage 1: fused GRU1 + attention over 65536 sequences (T=5, F=16)
    // persistent: 148 CTAs grid-stride over 4096 batches of 16 seqs
    gru_mma<5, true><<<148, 512, smem1>>>(
        sf, WiB, WB1, g1bih, g1bhh, a1w, a1b, shortb, 4096);

    // Stage 2: intra-sector GAT on last week's embedding
    gat_prep<<<2048, 128>>>(shortb + 31 * 128, 32 * 128, giW, gia, Wh, s12, 2048);
    gat_intra_attn<<<2048, 128>>>(Wh, s12, sect, intra);

    // Stage 3: lg = single-step GRU (h0=0, T=1 attn = identity)
    gemm_bf16<<<dim3(2048 / 64, 6), 256, smemG>>>(intra, ggWih, ggbih, gi);
    gru_single<<<1024, 256>>>(gi, ggbhh, lgv);

    // Stage 4: la = GRU over 32 weekly embeddings (T=32), pooling fused
    gemm_bf16<<<dim3(65536 / 64, 6), 256, smemG>>>(shortb, gaWih, gabih, gi);
    gru_mma<32, false><<<128, 512, smem4>>>(
        gi, nullptr, WB4, nullptr, gabhh, aaw, aab, lav, 128);

    // Stage 5: sector aggregation + inter-sector GAT
    sector_mean<<<16, 128>>>(lgv, sect, sec);
    gat_prep<<<16, 128>>>(sec, 128, geW, gea, Wh2, s12b, 16);
    gat_inter_attn<<<16, 128>>>(Wh2, s12b, adj, secout);

    // Stage 6: fusion + heads
    fusion_heads<<<2048, 128>>>(lgv, lav, secout, sect, fw, fb, rw, rb, mw, mb, out);
}